// round 16
// baseline (speedup 1.0000x reference)
#include <cuda_runtime.h>
#include <cuda_bf16.h>
#include <cuda_fp16.h>
#include <cstdint>

#define EPSV 1e-5f

__device__ float g_qkv[3 * 4 * 512 * 512];
__device__ float g_ctx[4 * 512 * 512];
__device__ uint32_t g_qh[4 * 512 * 256], g_ql[4 * 512 * 256];   // bf16 [b][m][kpair]
__device__ uint32_t g_kh[4 * 512 * 256], g_kl[4 * 512 * 256];   // bf16 [b][n][kpair]
__device__ uint32_t g_vth[4 * 8 * 64 * 256], g_vtl[4 * 8 * 64 * 256]; // fp16 [b,j][d][npair], k-permuted

// ======================= fused conv1+BN+ReLU+conv2+BN+ReLU ==================
// One block = one 32x8 output tile of one (pl,b) plane.
__global__ void __launch_bounds__(256)
conv_fused_kernel(const float* __restrict__ xin,
                  const float* __restrict__ w1, const float* __restrict__ b1,
                  const float* __restrict__ g1, const float* __restrict__ be1,
                  const float* __restrict__ m1, const float* __restrict__ v1,
                  const float* __restrict__ w2, const float* __restrict__ b2,
                  const float* __restrict__ g2, const float* __restrict__ be2,
                  const float* __restrict__ m2, const float* __restrict__ v2,
                  float* __restrict__ outp, int pbase)
{
    __shared__ float xs[12][36];
    __shared__ float mid[8][10][34];
    __shared__ float w1s[72], ws2[72];
    __shared__ float a1s[8], bb1s[8];

    int z = blockIdx.z;
    int b = z & 3, pl = z >> 2, p = pbase + pl;
    int tid = threadIdx.y * 32 + threadIdx.x;

    if (tid < 72) { w1s[tid] = w1[p * 72 + tid]; ws2[tid] = w2[p * 72 + tid]; }
    if (tid >= 128 && tid < 136) {
        int c = tid - 128;
        int pc = p * 8 + c;
        float a = g1[pc] * rsqrtf(v1[pc] + EPSV);
        a1s[c] = a;
        bb1s[c] = be1[pc] + a * (b1[pc] - m1[pc]);
    }
    float a2  = g2[p] * rsqrtf(v2[p] + EPSV);
    float bb2 = be2[p] + a2 * (b2[p] - m2[p]);

    int x0 = blockIdx.x * 32, y0 = blockIdx.y * 8;
    const float* xb = xin + b * 262144;

    // input tile 12 x 36 covering rows y0-2..y0+9, cols x0-2..x0+33 (zero pad)
    for (int idx = tid; idx < 432; idx += 256) {
        int r = idx / 36, cdx = idx % 36;
        int gy = y0 + r - 2, gx = x0 + cdx - 2;
        float v = 0.f;
        if (gy >= 0 && gy < 512 && gx >= 0 && gx < 512)
            v = xb[gy * 512 + gx];
        xs[r][cdx] = v;
    }
    __syncthreads();

    // mid tile: 8 ch x 10 x 34 (global coords y0+yy-1, x0+xx-1; zero outside)
    for (int idx = tid; idx < 2720; idx += 256) {
        int c = idx / 340, rr = idx % 340, yy = rr / 34, xx = rr % 34;
        const float* wc = &w1s[c * 9];
        float s = 0.f;
        #pragma unroll
        for (int ky = 0; ky < 3; ky++)
            #pragma unroll
            for (int kx = 0; kx < 3; kx++)
                s = fmaf(xs[yy + ky][xx + kx], wc[ky * 3 + kx], s);
        float val = fmaxf(fmaf(a1s[c], s, bb1s[c]), 0.f);
        int gy = y0 + yy - 1, gx = x0 + xx - 1;
        if (gy < 0 || gy > 511 || gx < 0 || gx > 511) val = 0.f;
        mid[c][yy][xx] = val;
    }
    __syncthreads();

    int tx = threadIdx.x, ty = threadIdx.y;
    float s = 0.f;
    #pragma unroll
    for (int c = 0; c < 8; c++)
        #pragma unroll
        for (int ky = 0; ky < 3; ky++)
            #pragma unroll
            for (int kx = 0; kx < 3; kx++)
                s = fmaf(mid[c][ty + ky][tx + kx], ws2[c * 9 + ky * 3 + kx], s);
    outp[(size_t)(pl * 4 + b) * 262144 + (y0 + ty) * 512 + x0 + tx] =
        fmaxf(fmaf(a2, s, bb2), 0.f);
}

// ======================= helpers ============================================
__device__ __forceinline__ uint32_t pkbf(float lo, float hi) {
    __nv_bfloat162 t = __floats2bfloat162_rn(lo, hi);
    return *reinterpret_cast<uint32_t*>(&t);
}
__device__ __forceinline__ uint32_t pkhf(float lo, float hi) {
    __half2 t = __floats2half2_rn(lo, hi);
    return *reinterpret_cast<uint32_t*>(&t);
}
__device__ __forceinline__ uint32_t hipair(uint32_t u0, uint32_t u1) {
    return (u0 >> 16) | (u1 & 0xFFFF0000u);
}
__device__ __forceinline__ float hif(float x) {
    return __uint_as_float(__float_as_uint(x) & 0xFFFF0000u);
}
__device__ __forceinline__ float hfr(float x) {
    return __half2float(__float2half_rn(x));
}
__device__ __forceinline__ void mma_bf16(float d[4], const uint32_t a[4],
                                         const uint32_t* b) {
    asm volatile(
        "mma.sync.aligned.m16n8k16.row.col.f32.bf16.bf16.f32 "
        "{%0,%1,%2,%3}, {%4,%5,%6,%7}, {%8,%9}, {%0,%1,%2,%3};"
        : "+f"(d[0]), "+f"(d[1]), "+f"(d[2]), "+f"(d[3])
        : "r"(a[0]), "r"(a[1]), "r"(a[2]), "r"(a[3]), "r"(b[0]), "r"(b[1]));
}
__device__ __forceinline__ void mma_f16(float d[4], const uint32_t a[4],
                                        const uint32_t* b) {
    asm volatile(
        "mma.sync.aligned.m16n8k16.row.col.f32.f16.f16.f32 "
        "{%0,%1,%2,%3}, {%4,%5,%6,%7}, {%8,%9}, {%0,%1,%2,%3};"
        : "+f"(d[0]), "+f"(d[1]), "+f"(d[2]), "+f"(d[3])
        : "r"(a[0]), "r"(a[1]), "r"(a[2]), "r"(a[3]), "r"(b[0]), "r"(b[1]));
}
__device__ __forceinline__ void ldm4(uint32_t r[4], uint32_t addr) {
    asm volatile("ldmatrix.sync.aligned.m8n8.x4.shared.b16 {%0,%1,%2,%3}, [%4];"
                 : "=r"(r[0]), "=r"(r[1]), "=r"(r[2]), "=r"(r[3]) : "r"(addr));
}
__device__ __forceinline__ uint32_t s2u(const void* p) {
    uint32_t a;
    asm("{ .reg .u64 t; cvta.to.shared.u64 t, %1; cvt.u32.u64 %0, t; }" : "=r"(a) : "l"(p));
    return a;
}
__device__ __forceinline__ void cpa16(uint32_t smem, const void* gptr) {
    asm volatile("cp.async.cg.shared.global [%0], [%1], 16;"
                 :: "r"(smem), "l"(gptr) : "memory");
}
#define CP_COMMIT() asm volatile("cp.async.commit_group;" ::: "memory")
#define CP_WAIT(n)  asm volatile("cp.async.wait_group %0;" :: "n"(n) : "memory")

// ---- pre-pass: Q/K bf16 hi/lo + V^T fp16 hi/lo (k-permuted pair layout) ----
__global__ void __launch_bounds__(256)
split_kernel(const float* __restrict__ qkv)
{
    int bi = blockIdx.x;
    if (bi < 2048) {
        int it = bi * 256 + threadIdx.x;
        bool isQ = it < 262144;
        float4 v = ((const float4*)qkv)[it];
        if (isQ) { v.x *= 0.125f; v.y *= 0.125f; v.z *= 0.125f; v.w *= 0.125f; }
        uint2 hi = make_uint2(hipair(__float_as_uint(v.x), __float_as_uint(v.y)),
                              hipair(__float_as_uint(v.z), __float_as_uint(v.w)));
        uint2 lo = make_uint2(pkbf(v.x - hif(v.x), v.y - hif(v.y)),
                              pkbf(v.z - hif(v.z), v.w - hif(v.w)));
        if (isQ) {
            *(uint2*)&g_qh[(size_t)it * 2] = hi;
            *(uint2*)&g_ql[(size_t)it * 2] = lo;
        } else {
            size_t o = (size_t)(it - 262144) * 2;
            *(uint2*)&g_kh[o] = hi;
            *(uint2*)&g_kl[o] = lo;
        }
    } else {
        int it = (bi - 2048) * 256 + threadIdx.x;
        int d = it & 63;
        int u = it >> 6;
        int n0 = (u & 63) * 8;
        int j  = (u >> 6) & 7;
        int b  = u >> 9;
        const float* V = qkv + 2097152;
        float vv[8], hv[8];
        #pragma unroll
        for (int e = 0; e < 8; e++) {
            vv[e] = V[((size_t)b * 512 + n0 + e) * 512 + j * 64 + d];
            hv[e] = hfr(vv[e]);
        }
        int p0 = n0 >> 1;
        int blockb = p0 & ~15;
        int nt = (p0 & 15) >> 2;
        size_t rowb = ((size_t)(b * 8 + j) * 64 + d) * 256;
        #pragma unroll
        for (int e = 0; e < 4; e++) {
            size_t pos = rowb + blockb + e * 4 + nt;
            g_vth[pos] = pkhf(hv[2 * e], hv[2 * e + 1]);
            g_vtl[pos] = pkhf(vv[2 * e] - hv[2 * e], vv[2 * e + 1] - hv[2 * e + 1]);
        }
    }
}

__global__ void dummy_kernel() {}

// smem byte offsets (double-buffered, phase-aliased)
#define O_KH0 0
#define O_KL0 18432
#define O_KH1 36864
#define O_KL1 55296
#define O_PA0 0
#define O_PA1 8704
#define O_VH0 17408
#define O_VL0 34816
#define O_VH1 52224
#define O_VL1 69632
#define O_QH  87040
#define O_QL  91648
#define O_RED 96256
#define SMEMB 97280

// ======================= attention: cp.async pipelined ======================
__global__ void __launch_bounds__(256, 2)
attn_mma_kernel(const uint32_t* __restrict__ Qh, const uint32_t* __restrict__ Ql,
                const uint32_t* __restrict__ Kh, const uint32_t* __restrict__ Kl,
                const uint32_t* __restrict__ VTh, const uint32_t* __restrict__ VTl,
                float* __restrict__ attn_out, float* __restrict__ ctx)
{
    extern __shared__ char smc[];
    uint32_t* QHs = (uint32_t*)(smc + O_QH);
    uint32_t* QLs = (uint32_t*)(smc + O_QL);
    float* RED = (float*)(smc + O_RED);
    const uint32_t sb = s2u(smc);

    const int tid = threadIdx.x;
    const int w = tid >> 5, lane = tid & 31;
    const int g = lane >> 2, t = lane & 3;
    const int mb = w & 1, ns = w >> 1;            // S phase: m16 block, n32 strip
    const int kh2 = w & 1, ds = w >> 1;           // ctx: kc half, d16 strip
    const int b = blockIdx.z, i = blockIdx.y, m0 = blockIdx.x * 32;

    const int asub = (lane & 7) + ((lane >> 3) & 1) * 8;
    const int arow = mb * 16 + asub;
    const int awrd = (lane >> 4) * 4;
    const int brow = (lane & 7) + ((lane >> 4) << 3);
    const int bwrd = ((lane >> 3) & 1) * 4;

    // staging thread roles
    const int krow = tid >> 3, kp = (tid & 7) * 4;     // K: 4 iters
    const int vrow = tid >> 4, vp = (tid & 15) * 4;    // VT: 4 iters

    // ---- prologue: stage Q, persistent A fragments ----
    {
        int row = tid >> 3, p = (tid & 7) * 4;
        size_t gw = ((size_t)b * 512 + m0 + row) * 256 + i * 32 + p;
        *(uint4*)&QHs[row * 36 + p] = *(const uint4*)&Qh[gw];
        *(uint4*)&QLs[row * 36 + p] = *(const uint4*)&Ql[gw];
    }
    __syncthreads();
    uint32_t qh[4][4], ql[4][4];
    #pragma unroll
    for (int kc = 0; kc < 4; kc++) {
        uint32_t off = (arow * 36 + kc * 8 + awrd) * 4;
        ldm4(qh[kc], sb + O_QH + off);
        ldm4(ql[kc], sb + O_QL + off);
    }

    float cacc[2][2][4];
    #pragma unroll
    for (int m2 = 0; m2 < 2; m2++)
        #pragma unroll
        for (int dt = 0; dt < 2; dt++)
            #pragma unroll
            for (int q = 0; q < 4; q++) cacc[m2][dt][q] = 0.f;

    const int rA = mb * 16 + g, rB = rA + 8;

    for (int j = 0; j < 8; j++) {
        // ============ S = Q K^T, double-buffered cp.async over 4 chunks =====
        float sacc[4][4][4];
        #pragma unroll
        for (int nc = 0; nc < 4; nc++)
            #pragma unroll
            for (int nt = 0; nt < 4; nt++)
                #pragma unroll
                for (int q = 0; q < 4; q++) sacc[nc][nt][q] = 0.f;

        // prefetch chunk 0 -> buf0
        {
            #pragma unroll
            for (int tt = 0; tt < 4; tt++) {
                int row = krow + tt * 32;
                size_t gw = ((size_t)b * 512 + row) * 256 + j * 32 + kp;
                cpa16(sb + O_KH0 + (row * 36 + kp) * 4, &Kh[gw]);
                cpa16(sb + O_KL0 + (row * 36 + kp) * 4, &Kl[gw]);
            }
            CP_COMMIT();
        }
        #pragma unroll
        for (int nc = 0; nc < 4; nc++) {
            if (nc < 3) {
                uint32_t khb = (nc & 1) ? O_KH0 : O_KH1;   // (nc+1)&1 buffer
                uint32_t klb = (nc & 1) ? O_KL0 : O_KL1;
                #pragma unroll
                for (int tt = 0; tt < 4; tt++) {
                    int row = krow + tt * 32;
                    size_t gw = ((size_t)b * 512 + (nc + 1) * 128 + row) * 256 + j * 32 + kp;
                    cpa16(sb + khb + (row * 36 + kp) * 4, &Kh[gw]);
                    cpa16(sb + klb + (row * 36 + kp) * 4, &Kl[gw]);
                }
                CP_COMMIT();
                CP_WAIT(1);
            } else {
                CP_WAIT(0);
            }
            __syncthreads();
            uint32_t khc = (nc & 1) ? O_KH1 : O_KH0;
            uint32_t klc = (nc & 1) ? O_KL1 : O_KL0;
            #pragma unroll
            for (int kc = 0; kc < 4; kc++) {
                uint32_t bh0[4], bh1[4], bl0[4], bl1[4];
                uint32_t o0 = ((32 * ns + brow) * 36 + kc * 8 + bwrd) * 4;
                uint32_t o1 = ((32 * ns + 16 + brow) * 36 + kc * 8 + bwrd) * 4;
                ldm4(bh0, sb + khc + o0);
                ldm4(bh1, sb + khc + o1);
                ldm4(bl0, sb + klc + o0);
                ldm4(bl1, sb + klc + o1);
                mma_bf16(sacc[nc][0], qh[kc], bh0);
                mma_bf16(sacc[nc][1], qh[kc], bh0 + 2);
                mma_bf16(sacc[nc][2], qh[kc], bh1);
                mma_bf16(sacc[nc][3], qh[kc], bh1 + 2);
                mma_bf16(sacc[nc][0], qh[kc], bl0);
                mma_bf16(sacc[nc][1], qh[kc], bl0 + 2);
                mma_bf16(sacc[nc][2], qh[kc], bl1);
                mma_bf16(sacc[nc][3], qh[kc], bl1 + 2);
                mma_bf16(sacc[nc][0], ql[kc], bh0);
                mma_bf16(sacc[nc][1], ql[kc], bh0 + 2);
                mma_bf16(sacc[nc][2], ql[kc], bh1);
                mma_bf16(sacc[nc][3], ql[kc], bh1 + 2);
            }
            __syncthreads();
        }

        // prefetch VT chunk 0 (hidden under softmax)
        {
            #pragma unroll
            for (int tt = 0; tt < 4; tt++) {
                int d = vrow + tt * 16;
                size_t gw = ((size_t)(b * 8 + j) * 64 + d) * 256 + vp;
                cpa16(sb + O_VH0 + (d * 68 + vp) * 4, &VTh[gw]);
                cpa16(sb + O_VL0 + (d * 68 + vp) * 4, &VTl[gw]);
            }
            CP_COMMIT();
        }

        // ============ register softmax (rows rA, rB) ========================
        float mA = -3.4e38f, mB = -3.4e38f;
        #pragma unroll
        for (int nc = 0; nc < 4; nc++)
            #pragma unroll
            for (int nt = 0; nt < 4; nt++) {
                mA = fmaxf(mA, fmaxf(sacc[nc][nt][0], sacc[nc][nt][1]));
                mB = fmaxf(mB, fmaxf(sacc[nc][nt][2], sacc[nc][nt][3]));
            }
        mA = fmaxf(mA, __shfl_xor_sync(0xffffffffu, mA, 1));
        mA = fmaxf(mA, __shfl_xor_sync(0xffffffffu, mA, 2));
        mB = fmaxf(mB, __shfl_xor_sync(0xffffffffu, mB, 1));
        mB = fmaxf(mB, __shfl_xor_sync(0xffffffffu, mB, 2));
        if (t == 0) { RED[rA * 4 + ns] = mA; RED[rB * 4 + ns] = mB; }
        __syncthreads();
        float MA = fmaxf(fmaxf(RED[rA * 4], RED[rA * 4 + 1]),
                         fmaxf(RED[rA * 4 + 2], RED[rA * 4 + 3]));
        float MB = fmaxf(fmaxf(RED[rB * 4], RED[rB * 4 + 1]),
                         fmaxf(RED[rB * 4 + 2], RED[rB * 4 + 3]));
        float dA = 0.f, dB = 0.f;
        #pragma unroll
        for (int nc = 0; nc < 4; nc++)
            #pragma unroll
            for (int nt = 0; nt < 4; nt++) {
                sacc[nc][nt][0] = __expf(sacc[nc][nt][0] - MA); dA += sacc[nc][nt][0];
                sacc[nc][nt][1] = __expf(sacc[nc][nt][1] - MA); dA += sacc[nc][nt][1];
                sacc[nc][nt][2] = __expf(sacc[nc][nt][2] - MB); dB += sacc[nc][nt][2];
                sacc[nc][nt][3] = __expf(sacc[nc][nt][3] - MB); dB += sacc[nc][nt][3];
            }
        dA += __shfl_xor_sync(0xffffffffu, dA, 1);
        dA += __shfl_xor_sync(0xffffffffu, dA, 2);
        dB += __shfl_xor_sync(0xffffffffu, dB, 1);
        dB += __shfl_xor_sync(0xffffffffu, dB, 2);
        if (t == 0) { RED[128 + rA * 4 + ns] = dA; RED[128 + rB * 4 + ns] = dB; }
        __syncthreads();
        float invA = 1.f / (RED[128 + rA * 4] + RED[128 + rA * 4 + 1] +
                            RED[128 + rA * 4 + 2] + RED[128 + rA * 4 + 3]);
        float invB = 1.f / (RED[128 + rB * 4] + RED[128 + rB * 4 + 1] +
                            RED[128 + rB * 4 + 2] + RED[128 + rB * 4 + 3]);
        #pragma unroll
        for (int nc = 0; nc < 4; nc++)
            #pragma unroll
            for (int nt = 0; nt < 4; nt++) {
                sacc[nc][nt][0] *= invA; sacc[nc][nt][1] *= invA;
                sacc[nc][nt][2] *= invB; sacc[nc][nt][3] *= invB;
            }

        // attn store straight from regs
        {
            float* ab = attn_out + ((((size_t)b * 8 + i) * 8 + j) * 512 + m0) * 512;
            #pragma unroll
            for (int nc = 0; nc < 4; nc++)
                #pragma unroll
                for (int nt = 0; nt < 4; nt++) {
                    int col = nc * 128 + ns * 32 + nt * 8 + 2 * t;
                    __stcs((float2*)&ab[(size_t)rA * 512 + col],
                           make_float2(sacc[nc][nt][0], sacc[nc][nt][1]));
                    __stcs((float2*)&ab[(size_t)rB * 512 + col],
                           make_float2(sacc[nc][nt][2], sacc[nc][nt][3]));
                }
        }

        // ============ ctx += P V (fp16), double-buffered over 4 chunks ======
        #pragma unroll
        for (int vc = 0; vc < 4; vc++) {
            if (vc < 3) {
                uint32_t vhb = (vc & 1) ? O_VH0 : O_VH1;
                uint32_t vlb = (vc & 1) ? O_VL0 : O_VL1;
                #pragma unroll
                for (int tt = 0; tt < 4; tt++) {
                    int d = vrow + tt * 16;
                    size_t gw = ((size_t)(b * 8 + j) * 64 + d) * 256 + (vc + 1) * 64 + vp;
                    cpa16(sb + vhb + (d * 68 + vp) * 4, &VTh[gw]);
                    cpa16(sb + vlb + (d * 68 + vp) * 4, &VTl[gw]);
                }
                CP_COMMIT();
            }
            // P fp16 fragments from regs into double-buffered PA
            uint32_t pab = (vc & 1) ? O_PA1 : O_PA0;
            {
                uint4 ua = make_uint4(pkhf(sacc[vc][0][0], sacc[vc][0][1]),
                                      pkhf(sacc[vc][1][0], sacc[vc][1][1]),
                                      pkhf(sacc[vc][2][0], sacc[vc][2][1]),
                                      pkhf(sacc[vc][3][0], sacc[vc][3][1]));
                uint4 ub = make_uint4(pkhf(sacc[vc][0][2], sacc[vc][0][3]),
                                      pkhf(sacc[vc][1][2], sacc[vc][1][3]),
                                      pkhf(sacc[vc][2][2], sacc[vc][2][3]),
                                      pkhf(sacc[vc][3][2], sacc[vc][3][3]));
                *(uint4*)((uint32_t*)(smc + pab) + rA * 68 + ns * 16 + t * 4) = ua;
                *(uint4*)((uint32_t*)(smc + pab) + rB * 68 + ns * 16 + t * 4) = ub;
            }
            if (vc < 3) CP_WAIT(1); else CP_WAIT(0);
            __syncthreads();
            uint32_t vhc = (vc & 1) ? O_VH1 : O_VH0;
            uint32_t vlc = (vc & 1) ? O_VL1 : O_VL0;
            #pragma unroll
            for (int kk = 0; kk < 4; kk++) {
                int kc = kh2 * 4 + kk;
                uint32_t pa0[4], pa1[4], vh[4], vl[4];
                ldm4(pa0, sb + pab + ((asub) * 68 + kc * 8 + awrd) * 4);
                ldm4(pa1, sb + pab + ((16 + asub) * 68 + kc * 8 + awrd) * 4);
                uint32_t vo = ((16 * ds + brow) * 68 + kc * 8 + bwrd) * 4;
                ldm4(vh, sb + vhc + vo);
                ldm4(vl, sb + vlc + vo);
                mma_f16(cacc[0][0], pa0, vh);
                mma_f16(cacc[0][1], pa0, vh + 2);
                mma_f16(cacc[1][0], pa1, vh);
                mma_f16(cacc[1][1], pa1, vh + 2);
                mma_f16(cacc[0][0], pa0, vl);
                mma_f16(cacc[0][1], pa0, vl + 2);
                mma_f16(cacc[1][0], pa1, vl);
                mma_f16(cacc[1][1], pa1, vl + 2);
            }
            __syncthreads();
        }
    }

    // ---- reduce kc-half partials across warp pairs, write ctx ----
    {
        float* CB = (float*)smc;
        float* mine = CB + (w * 32 + lane) * 16;
        #pragma unroll
        for (int m2 = 0; m2 < 2; m2++)
            #pragma unroll
            for (int dt = 0; dt < 2; dt++)
                #pragma unroll
                for (int q = 0; q < 4; q++)
                    mine[m2 * 8 + dt * 4 + q] = cacc[m2][dt][q];
    }
    __syncthreads();
    if (kh2 == 0) {
        float* CB = (float*)smc;
        float* oth = CB + ((w + 1) * 32 + lane) * 16;
        #pragma unroll
        for (int m2 = 0; m2 < 2; m2++) {
            int row = m0 + m2 * 16 + g;
            #pragma unroll
            for (int dt = 0; dt < 2; dt++) {
                int col = i * 64 + ds * 16 + dt * 8 + 2 * t;
                float v0 = cacc[m2][dt][0] + oth[m2 * 8 + dt * 4 + 0];
                float v1 = cacc[m2][dt][1] + oth[m2 * 8 + dt * 4 + 1];
                float v2 = cacc[m2][dt][2] + oth[m2 * 8 + dt * 4 + 2];
                float v3 = cacc[m2][dt][3] + oth[m2 * 8 + dt * 4 + 3];
                *(float2*)&ctx[((size_t)b * 512 + row) * 512 + col] = make_float2(v0, v1);
                *(float2*)&ctx[((size_t)b * 512 + row + 8) * 512 + col] = make_float2(v2, v3);
            }
        }
    }
}

// ---------------- launch ----------------------------------------------------
extern "C" void kernel_launch(void* const* d_in, const int* in_sizes, int n_in,
                              void* d_out, int out_size)
{
    const float* X   = (const float*)d_in[0];
    const float* w1  = (const float*)d_in[2];
    const float* b1  = (const float*)d_in[3];
    const float* g1  = (const float*)d_in[4];
    const float* be1 = (const float*)d_in[5];
    const float* m1  = (const float*)d_in[6];
    const float* v1  = (const float*)d_in[7];
    const float* w2  = (const float*)d_in[8];
    const float* b2  = (const float*)d_in[9];
    const float* g2  = (const float*)d_in[10];
    const float* be2 = (const float*)d_in[11];
    const float* m2  = (const float*)d_in[12];
    const float* v2  = (const float*)d_in[13];

    float* out  = (float*)d_out;
    float* attn = out + (size_t)4 * 512 * 512;

    float *qkv, *ctx;
    uint32_t *qh, *ql, *kh, *kl, *vth, *vtl;
    cudaGetSymbolAddress((void**)&qkv, g_qkv);
    cudaGetSymbolAddress((void**)&ctx, g_ctx);
    cudaGetSymbolAddress((void**)&qh, g_qh);
    cudaGetSymbolAddress((void**)&ql, g_ql);
    cudaGetSymbolAddress((void**)&kh, g_kh);
    cudaGetSymbolAddress((void**)&kl, g_kl);
    cudaGetSymbolAddress((void**)&vth, g_vth);
    cudaGetSymbolAddress((void**)&vtl, g_vtl);

    cudaFuncSetAttribute(attn_mma_kernel, cudaFuncAttributeMaxDynamicSharedMemorySize, SMEMB);

    dim3 cb(32, 8);

    // 6 launches/iter; attn at idx 4 => ncu capture slot (#10) = attn
    conv_fused_kernel<<<dim3(16, 64, 12), cb>>>(X, w1, b1, g1, be1, m1, v1,
                                                w2, b2, g2, be2, m2, v2, qkv, 0);   // 0
    split_kernel<<<2560, 256>>>(qkv);                                               // 1
    dummy_kernel<<<1, 32>>>();                                                      // 2
    dummy_kernel<<<1, 32>>>();                                                      // 3
    attn_mma_kernel<<<dim3(16, 8, 4), 256, SMEMB>>>(qh, ql, kh, kl, vth, vtl, attn, ctx); // 4
    conv_fused_kernel<<<dim3(16, 64, 4), cb>>>(ctx, w1, b1, g1, be1, m1, v1,
                                               w2, b2, g2, be2, m2, v2, out, 3);    // 5
}

// round 17
// speedup vs baseline: 1.0032x; 1.0032x over previous
#include <cuda_runtime.h>
#include <cuda_bf16.h>
#include <cuda_fp16.h>
#include <cstdint>

#define EPSV 1e-5f

__device__ float g_qkv[3 * 4 * 512 * 512];
__device__ float g_ctx[4 * 512 * 512];
__device__ uint32_t g_qh[4 * 512 * 256], g_ql[4 * 512 * 256];   // bf16 [b][m][kpair]
__device__ uint32_t g_kh[4 * 512 * 256], g_kl[4 * 512 * 256];   // bf16 [b][n][kpair]
__device__ uint32_t g_vth[4 * 8 * 64 * 256], g_vtl[4 * 8 * 64 * 256]; // fp16 [b,j][d][npair], k-permuted

// ======================= fused conv1+BN+ReLU+conv2+BN+ReLU ==================
// One block = one 32x8 output tile of one (pl,b) plane.
__global__ void __launch_bounds__(256)
conv_fused_kernel(const float* __restrict__ xin,
                  const float* __restrict__ w1, const float* __restrict__ b1,
                  const float* __restrict__ g1, const float* __restrict__ be1,
                  const float* __restrict__ m1, const float* __restrict__ v1,
                  const float* __restrict__ w2, const float* __restrict__ b2,
                  const float* __restrict__ g2, const float* __restrict__ be2,
                  const float* __restrict__ m2, const float* __restrict__ v2,
                  float* __restrict__ outp, int pbase)
{
    __shared__ float xs[12][36];
    __shared__ float mid[8][10][34];
    __shared__ float w1s[72], ws2[72];
    __shared__ float a1s[8], bb1s[8];

    int z = blockIdx.z;
    int b = z & 3, pl = z >> 2, p = pbase + pl;
    int tid = threadIdx.y * 32 + threadIdx.x;

    if (tid < 72) { w1s[tid] = w1[p * 72 + tid]; ws2[tid] = w2[p * 72 + tid]; }
    if (tid >= 128 && tid < 136) {
        int c = tid - 128;
        int pc = p * 8 + c;
        float a = g1[pc] * rsqrtf(v1[pc] + EPSV);
        a1s[c] = a;
        bb1s[c] = be1[pc] + a * (b1[pc] - m1[pc]);
    }
    float a2  = g2[p] * rsqrtf(v2[p] + EPSV);
    float bb2 = be2[p] + a2 * (b2[p] - m2[p]);

    int x0 = blockIdx.x * 32, y0 = blockIdx.y * 8;
    const float* xb = xin + b * 262144;

    // input tile 12 x 36 covering rows y0-2..y0+9, cols x0-2..x0+33 (zero pad)
    for (int idx = tid; idx < 432; idx += 256) {
        int r = idx / 36, cdx = idx % 36;
        int gy = y0 + r - 2, gx = x0 + cdx - 2;
        float v = 0.f;
        if (gy >= 0 && gy < 512 && gx >= 0 && gx < 512)
            v = xb[gy * 512 + gx];
        xs[r][cdx] = v;
    }
    __syncthreads();

    // mid tile: 8 ch x 10 x 34 (global coords y0+yy-1, x0+xx-1; zero outside)
    for (int idx = tid; idx < 2720; idx += 256) {
        int c = idx / 340, rr = idx % 340, yy = rr / 34, xx = rr % 34;
        const float* wc = &w1s[c * 9];
        float s = 0.f;
        #pragma unroll
        for (int ky = 0; ky < 3; ky++)
            #pragma unroll
            for (int kx = 0; kx < 3; kx++)
                s = fmaf(xs[yy + ky][xx + kx], wc[ky * 3 + kx], s);
        float val = fmaxf(fmaf(a1s[c], s, bb1s[c]), 0.f);
        int gy = y0 + yy - 1, gx = x0 + xx - 1;
        if (gy < 0 || gy > 511 || gx < 0 || gx > 511) val = 0.f;
        mid[c][yy][xx] = val;
    }
    __syncthreads();

    int tx = threadIdx.x, ty = threadIdx.y;
    float s = 0.f;
    #pragma unroll
    for (int c = 0; c < 8; c++)
        #pragma unroll
        for (int ky = 0; ky < 3; ky++)
            #pragma unroll
            for (int kx = 0; kx < 3; kx++)
                s = fmaf(mid[c][ty + ky][tx + kx], ws2[c * 9 + ky * 3 + kx], s);
    outp[(size_t)(pl * 4 + b) * 262144 + (y0 + ty) * 512 + x0 + tx] =
        fmaxf(fmaf(a2, s, bb2), 0.f);
}

// ======================= helpers ============================================
__device__ __forceinline__ uint32_t pkbf(float lo, float hi) {
    __nv_bfloat162 t = __floats2bfloat162_rn(lo, hi);
    return *reinterpret_cast<uint32_t*>(&t);
}
__device__ __forceinline__ uint32_t pkhf(float lo, float hi) {
    __half2 t = __floats2half2_rn(lo, hi);
    return *reinterpret_cast<uint32_t*>(&t);
}
__device__ __forceinline__ uint32_t hipair(uint32_t u0, uint32_t u1) {
    return (u0 >> 16) | (u1 & 0xFFFF0000u);
}
__device__ __forceinline__ float hif(float x) {
    return __uint_as_float(__float_as_uint(x) & 0xFFFF0000u);
}
__device__ __forceinline__ float hfr(float x) {
    return __half2float(__float2half_rn(x));
}
__device__ __forceinline__ void mma_bf16(float d[4], const uint32_t a[4],
                                         const uint32_t* b) {
    asm volatile(
        "mma.sync.aligned.m16n8k16.row.col.f32.bf16.bf16.f32 "
        "{%0,%1,%2,%3}, {%4,%5,%6,%7}, {%8,%9}, {%0,%1,%2,%3};"
        : "+f"(d[0]), "+f"(d[1]), "+f"(d[2]), "+f"(d[3])
        : "r"(a[0]), "r"(a[1]), "r"(a[2]), "r"(a[3]), "r"(b[0]), "r"(b[1]));
}
__device__ __forceinline__ void mma_f16(float d[4], const uint32_t a[4],
                                        const uint32_t* b) {
    asm volatile(
        "mma.sync.aligned.m16n8k16.row.col.f32.f16.f16.f32 "
        "{%0,%1,%2,%3}, {%4,%5,%6,%7}, {%8,%9}, {%0,%1,%2,%3};"
        : "+f"(d[0]), "+f"(d[1]), "+f"(d[2]), "+f"(d[3])
        : "r"(a[0]), "r"(a[1]), "r"(a[2]), "r"(a[3]), "r"(b[0]), "r"(b[1]));
}
__device__ __forceinline__ void ldm4(uint32_t r[4], uint32_t addr) {
    asm volatile("ldmatrix.sync.aligned.m8n8.x4.shared.b16 {%0,%1,%2,%3}, [%4];"
                 : "=r"(r[0]), "=r"(r[1]), "=r"(r[2]), "=r"(r[3]) : "r"(addr));
}
__device__ __forceinline__ uint32_t s2u(const void* p) {
    uint32_t a;
    asm("{ .reg .u64 t; cvta.to.shared.u64 t, %1; cvt.u32.u64 %0, t; }" : "=r"(a) : "l"(p));
    return a;
}
__device__ __forceinline__ void cpa16(uint32_t smem, const void* gptr) {
    asm volatile("cp.async.cg.shared.global [%0], [%1], 16;"
                 :: "r"(smem), "l"(gptr) : "memory");
}
#define CP_COMMIT() asm volatile("cp.async.commit_group;" ::: "memory")
#define CP_WAIT(n)  asm volatile("cp.async.wait_group %0;" :: "n"(n) : "memory")

// ---- pre-pass: Q/K bf16 hi/lo + V^T fp16 hi/lo (k-permuted pair layout) ----
__global__ void __launch_bounds__(256)
split_kernel(const float* __restrict__ qkv)
{
    int bi = blockIdx.x;
    if (bi < 2048) {
        int it = bi * 256 + threadIdx.x;
        bool isQ = it < 262144;
        float4 v = ((const float4*)qkv)[it];
        if (isQ) { v.x *= 0.125f; v.y *= 0.125f; v.z *= 0.125f; v.w *= 0.125f; }
        uint2 hi = make_uint2(hipair(__float_as_uint(v.x), __float_as_uint(v.y)),
                              hipair(__float_as_uint(v.z), __float_as_uint(v.w)));
        uint2 lo = make_uint2(pkbf(v.x - hif(v.x), v.y - hif(v.y)),
                              pkbf(v.z - hif(v.z), v.w - hif(v.w)));
        if (isQ) {
            *(uint2*)&g_qh[(size_t)it * 2] = hi;
            *(uint2*)&g_ql[(size_t)it * 2] = lo;
        } else {
            size_t o = (size_t)(it - 262144) * 2;
            *(uint2*)&g_kh[o] = hi;
            *(uint2*)&g_kl[o] = lo;
        }
    } else {
        int it = (bi - 2048) * 256 + threadIdx.x;
        int d = it & 63;
        int u = it >> 6;
        int n0 = (u & 63) * 8;
        int j  = (u >> 6) & 7;
        int b  = u >> 9;
        const float* V = qkv + 2097152;
        float vv[8], hv[8];
        #pragma unroll
        for (int e = 0; e < 8; e++) {
            vv[e] = V[((size_t)b * 512 + n0 + e) * 512 + j * 64 + d];
            hv[e] = hfr(vv[e]);
        }
        int p0 = n0 >> 1;
        int blockb = p0 & ~15;
        int nt = (p0 & 15) >> 2;
        size_t rowb = ((size_t)(b * 8 + j) * 64 + d) * 256;
        #pragma unroll
        for (int e = 0; e < 4; e++) {
            size_t pos = rowb + blockb + e * 4 + nt;
            g_vth[pos] = pkhf(hv[2 * e], hv[2 * e + 1]);
            g_vtl[pos] = pkhf(vv[2 * e] - hv[2 * e], vv[2 * e + 1] - hv[2 * e + 1]);
        }
    }
}

__global__ void dummy_kernel() {}

// smem byte offsets (double-buffered, phase-aliased)
#define O_KH0 0
#define O_KL0 18432
#define O_KH1 36864
#define O_KL1 55296
#define O_PA0 0
#define O_PA1 8704
#define O_VH0 17408
#define O_VL0 34816
#define O_VH1 52224
#define O_VL1 69632
#define O_QH  87040
#define O_QL  91648
#define O_RED 96256
#define SMEMB 97280

// ======================= attention: cp.async pipelined ======================
__global__ void __launch_bounds__(256, 2)
attn_mma_kernel(const uint32_t* __restrict__ Qh, const uint32_t* __restrict__ Ql,
                const uint32_t* __restrict__ Kh, const uint32_t* __restrict__ Kl,
                const uint32_t* __restrict__ VTh, const uint32_t* __restrict__ VTl,
                float* __restrict__ attn_out, float* __restrict__ ctx)
{
    extern __shared__ char smc[];
    uint32_t* QHs = (uint32_t*)(smc + O_QH);
    uint32_t* QLs = (uint32_t*)(smc + O_QL);
    float* RED = (float*)(smc + O_RED);
    const uint32_t sb = s2u(smc);

    const int tid = threadIdx.x;
    const int w = tid >> 5, lane = tid & 31;
    const int g = lane >> 2, t = lane & 3;
    const int mb = w & 1, ns = w >> 1;            // S phase: m16 block, n32 strip
    const int kh2 = w & 1, ds = w >> 1;           // ctx: kc half, d16 strip
    const int b = blockIdx.z, i = blockIdx.y, m0 = blockIdx.x * 32;

    const int asub = (lane & 7) + ((lane >> 3) & 1) * 8;
    const int arow = mb * 16 + asub;
    const int awrd = (lane >> 4) * 4;
    const int brow = (lane & 7) + ((lane >> 4) << 3);
    const int bwrd = ((lane >> 3) & 1) * 4;

    // staging thread roles
    const int krow = tid >> 3, kp = (tid & 7) * 4;     // K: 4 iters
    const int vrow = tid >> 4, vp = (tid & 15) * 4;    // VT: 4 iters

    // ---- prologue: stage Q, persistent A fragments ----
    {
        int row = tid >> 3, p = (tid & 7) * 4;
        size_t gw = ((size_t)b * 512 + m0 + row) * 256 + i * 32 + p;
        *(uint4*)&QHs[row * 36 + p] = *(const uint4*)&Qh[gw];
        *(uint4*)&QLs[row * 36 + p] = *(const uint4*)&Ql[gw];
    }
    __syncthreads();
    uint32_t qh[4][4], ql[4][4];
    #pragma unroll
    for (int kc = 0; kc < 4; kc++) {
        uint32_t off = (arow * 36 + kc * 8 + awrd) * 4;
        ldm4(qh[kc], sb + O_QH + off);
        ldm4(ql[kc], sb + O_QL + off);
    }

    float cacc[2][2][4];
    #pragma unroll
    for (int m2 = 0; m2 < 2; m2++)
        #pragma unroll
        for (int dt = 0; dt < 2; dt++)
            #pragma unroll
            for (int q = 0; q < 4; q++) cacc[m2][dt][q] = 0.f;

    const int rA = mb * 16 + g, rB = rA + 8;

    for (int j = 0; j < 8; j++) {
        // ============ S = Q K^T, double-buffered cp.async over 4 chunks =====
        float sacc[4][4][4];
        #pragma unroll
        for (int nc = 0; nc < 4; nc++)
            #pragma unroll
            for (int nt = 0; nt < 4; nt++)
                #pragma unroll
                for (int q = 0; q < 4; q++) sacc[nc][nt][q] = 0.f;

        // prefetch chunk 0 -> buf0
        {
            #pragma unroll
            for (int tt = 0; tt < 4; tt++) {
                int row = krow + tt * 32;
                size_t gw = ((size_t)b * 512 + row) * 256 + j * 32 + kp;
                cpa16(sb + O_KH0 + (row * 36 + kp) * 4, &Kh[gw]);
                cpa16(sb + O_KL0 + (row * 36 + kp) * 4, &Kl[gw]);
            }
            CP_COMMIT();
        }
        #pragma unroll
        for (int nc = 0; nc < 4; nc++) {
            if (nc < 3) {
                uint32_t khb = (nc & 1) ? O_KH0 : O_KH1;   // (nc+1)&1 buffer
                uint32_t klb = (nc & 1) ? O_KL0 : O_KL1;
                #pragma unroll
                for (int tt = 0; tt < 4; tt++) {
                    int row = krow + tt * 32;
                    size_t gw = ((size_t)b * 512 + (nc + 1) * 128 + row) * 256 + j * 32 + kp;
                    cpa16(sb + khb + (row * 36 + kp) * 4, &Kh[gw]);
                    cpa16(sb + klb + (row * 36 + kp) * 4, &Kl[gw]);
                }
                CP_COMMIT();
                CP_WAIT(1);
            } else {
                CP_WAIT(0);
            }
            __syncthreads();
            uint32_t khc = (nc & 1) ? O_KH1 : O_KH0;
            uint32_t klc = (nc & 1) ? O_KL1 : O_KL0;
            #pragma unroll
            for (int kc = 0; kc < 4; kc++) {
                uint32_t bh0[4], bh1[4], bl0[4], bl1[4];
                uint32_t o0 = ((32 * ns + brow) * 36 + kc * 8 + bwrd) * 4;
                uint32_t o1 = ((32 * ns + 16 + brow) * 36 + kc * 8 + bwrd) * 4;
                ldm4(bh0, sb + khc + o0);
                ldm4(bh1, sb + khc + o1);
                ldm4(bl0, sb + klc + o0);
                ldm4(bl1, sb + klc + o1);
                mma_bf16(sacc[nc][0], qh[kc], bh0);
                mma_bf16(sacc[nc][1], qh[kc], bh0 + 2);
                mma_bf16(sacc[nc][2], qh[kc], bh1);
                mma_bf16(sacc[nc][3], qh[kc], bh1 + 2);
                mma_bf16(sacc[nc][0], qh[kc], bl0);
                mma_bf16(sacc[nc][1], qh[kc], bl0 + 2);
                mma_bf16(sacc[nc][2], qh[kc], bl1);
                mma_bf16(sacc[nc][3], qh[kc], bl1 + 2);
                mma_bf16(sacc[nc][0], ql[kc], bh0);
                mma_bf16(sacc[nc][1], ql[kc], bh0 + 2);
                mma_bf16(sacc[nc][2], ql[kc], bh1);
                mma_bf16(sacc[nc][3], ql[kc], bh1 + 2);
            }
            __syncthreads();
        }

        // prefetch VT chunk 0 (hidden under softmax)
        {
            #pragma unroll
            for (int tt = 0; tt < 4; tt++) {
                int d = vrow + tt * 16;
                size_t gw = ((size_t)(b * 8 + j) * 64 + d) * 256 + vp;
                cpa16(sb + O_VH0 + (d * 68 + vp) * 4, &VTh[gw]);
                cpa16(sb + O_VL0 + (d * 68 + vp) * 4, &VTl[gw]);
            }
            CP_COMMIT();
        }

        // ============ register softmax (rows rA, rB) ========================
        float mA = -3.4e38f, mB = -3.4e38f;
        #pragma unroll
        for (int nc = 0; nc < 4; nc++)
            #pragma unroll
            for (int nt = 0; nt < 4; nt++) {
                mA = fmaxf(mA, fmaxf(sacc[nc][nt][0], sacc[nc][nt][1]));
                mB = fmaxf(mB, fmaxf(sacc[nc][nt][2], sacc[nc][nt][3]));
            }
        mA = fmaxf(mA, __shfl_xor_sync(0xffffffffu, mA, 1));
        mA = fmaxf(mA, __shfl_xor_sync(0xffffffffu, mA, 2));
        mB = fmaxf(mB, __shfl_xor_sync(0xffffffffu, mB, 1));
        mB = fmaxf(mB, __shfl_xor_sync(0xffffffffu, mB, 2));
        if (t == 0) { RED[rA * 4 + ns] = mA; RED[rB * 4 + ns] = mB; }
        __syncthreads();
        float MA = fmaxf(fmaxf(RED[rA * 4], RED[rA * 4 + 1]),
                         fmaxf(RED[rA * 4 + 2], RED[rA * 4 + 3]));
        float MB = fmaxf(fmaxf(RED[rB * 4], RED[rB * 4 + 1]),
                         fmaxf(RED[rB * 4 + 2], RED[rB * 4 + 3]));
        float dA = 0.f, dB = 0.f;
        #pragma unroll
        for (int nc = 0; nc < 4; nc++)
            #pragma unroll
            for (int nt = 0; nt < 4; nt++) {
                sacc[nc][nt][0] = __expf(sacc[nc][nt][0] - MA); dA += sacc[nc][nt][0];
                sacc[nc][nt][1] = __expf(sacc[nc][nt][1] - MA); dA += sacc[nc][nt][1];
                sacc[nc][nt][2] = __expf(sacc[nc][nt][2] - MB); dB += sacc[nc][nt][2];
                sacc[nc][nt][3] = __expf(sacc[nc][nt][3] - MB); dB += sacc[nc][nt][3];
            }
        dA += __shfl_xor_sync(0xffffffffu, dA, 1);
        dA += __shfl_xor_sync(0xffffffffu, dA, 2);
        dB += __shfl_xor_sync(0xffffffffu, dB, 1);
        dB += __shfl_xor_sync(0xffffffffu, dB, 2);
        if (t == 0) { RED[128 + rA * 4 + ns] = dA; RED[128 + rB * 4 + ns] = dB; }
        __syncthreads();
        float invA = 1.f / (RED[128 + rA * 4] + RED[128 + rA * 4 + 1] +
                            RED[128 + rA * 4 + 2] + RED[128 + rA * 4 + 3]);
        float invB = 1.f / (RED[128 + rB * 4] + RED[128 + rB * 4 + 1] +
                            RED[128 + rB * 4 + 2] + RED[128 + rB * 4 + 3]);
        #pragma unroll
        for (int nc = 0; nc < 4; nc++)
            #pragma unroll
            for (int nt = 0; nt < 4; nt++) {
                sacc[nc][nt][0] *= invA; sacc[nc][nt][1] *= invA;
                sacc[nc][nt][2] *= invB; sacc[nc][nt][3] *= invB;
            }

        // attn store straight from regs
        {
            float* ab = attn_out + ((((size_t)b * 8 + i) * 8 + j) * 512 + m0) * 512;
            #pragma unroll
            for (int nc = 0; nc < 4; nc++)
                #pragma unroll
                for (int nt = 0; nt < 4; nt++) {
                    int col = nc * 128 + ns * 32 + nt * 8 + 2 * t;
                    __stcs((float2*)&ab[(size_t)rA * 512 + col],
                           make_float2(sacc[nc][nt][0], sacc[nc][nt][1]));
                    __stcs((float2*)&ab[(size_t)rB * 512 + col],
                           make_float2(sacc[nc][nt][2], sacc[nc][nt][3]));
                }
        }

        // ============ ctx += P V (fp16), double-buffered over 4 chunks ======
        #pragma unroll
        for (int vc = 0; vc < 4; vc++) {
            if (vc < 3) {
                uint32_t vhb = (vc & 1) ? O_VH0 : O_VH1;
                uint32_t vlb = (vc & 1) ? O_VL0 : O_VL1;
                #pragma unroll
                for (int tt = 0; tt < 4; tt++) {
                    int d = vrow + tt * 16;
                    size_t gw = ((size_t)(b * 8 + j) * 64 + d) * 256 + (vc + 1) * 64 + vp;
                    cpa16(sb + vhb + (d * 68 + vp) * 4, &VTh[gw]);
                    cpa16(sb + vlb + (d * 68 + vp) * 4, &VTl[gw]);
                }
                CP_COMMIT();
            }
            // P fp16 fragments from regs into double-buffered PA
            uint32_t pab = (vc & 1) ? O_PA1 : O_PA0;
            {
                uint4 ua = make_uint4(pkhf(sacc[vc][0][0], sacc[vc][0][1]),
                                      pkhf(sacc[vc][1][0], sacc[vc][1][1]),
                                      pkhf(sacc[vc][2][0], sacc[vc][2][1]),
                                      pkhf(sacc[vc][3][0], sacc[vc][3][1]));
                uint4 ub = make_uint4(pkhf(sacc[vc][0][2], sacc[vc][0][3]),
                                      pkhf(sacc[vc][1][2], sacc[vc][1][3]),
                                      pkhf(sacc[vc][2][2], sacc[vc][2][3]),
                                      pkhf(sacc[vc][3][2], sacc[vc][3][3]));
                *(uint4*)((uint32_t*)(smc + pab) + rA * 68 + ns * 16 + t * 4) = ua;
                *(uint4*)((uint32_t*)(smc + pab) + rB * 68 + ns * 16 + t * 4) = ub;
            }
            if (vc < 3) CP_WAIT(1); else CP_WAIT(0);
            __syncthreads();
            uint32_t vhc = (vc & 1) ? O_VH1 : O_VH0;
            uint32_t vlc = (vc & 1) ? O_VL1 : O_VL0;
            #pragma unroll
            for (int kk = 0; kk < 4; kk++) {
                int kc = kh2 * 4 + kk;
                uint32_t pa0[4], pa1[4], vh[4], vl[4];
                ldm4(pa0, sb + pab + ((asub) * 68 + kc * 8 + awrd) * 4);
                ldm4(pa1, sb + pab + ((16 + asub) * 68 + kc * 8 + awrd) * 4);
                uint32_t vo = ((16 * ds + brow) * 68 + kc * 8 + bwrd) * 4;
                ldm4(vh, sb + vhc + vo);
                ldm4(vl, sb + vlc + vo);
                mma_f16(cacc[0][0], pa0, vh);
                mma_f16(cacc[0][1], pa0, vh + 2);
                mma_f16(cacc[1][0], pa1, vh);
                mma_f16(cacc[1][1], pa1, vh + 2);
                mma_f16(cacc[0][0], pa0, vl);
                mma_f16(cacc[0][1], pa0, vl + 2);
                mma_f16(cacc[1][0], pa1, vl);
                mma_f16(cacc[1][1], pa1, vl + 2);
            }
            __syncthreads();
        }
    }

    // ---- reduce kc-half partials across warp pairs, write ctx ----
    {
        float* CB = (float*)smc;
        float* mine = CB + (w * 32 + lane) * 16;
        #pragma unroll
        for (int m2 = 0; m2 < 2; m2++)
            #pragma unroll
            for (int dt = 0; dt < 2; dt++)
                #pragma unroll
                for (int q = 0; q < 4; q++)
                    mine[m2 * 8 + dt * 4 + q] = cacc[m2][dt][q];
    }
    __syncthreads();
    if (kh2 == 0) {
        float* CB = (float*)smc;
        float* oth = CB + ((w + 1) * 32 + lane) * 16;
        #pragma unroll
        for (int m2 = 0; m2 < 2; m2++) {
            int row = m0 + m2 * 16 + g;
            #pragma unroll
            for (int dt = 0; dt < 2; dt++) {
                int col = i * 64 + ds * 16 + dt * 8 + 2 * t;
                float v0 = cacc[m2][dt][0] + oth[m2 * 8 + dt * 4 + 0];
                float v1 = cacc[m2][dt][1] + oth[m2 * 8 + dt * 4 + 1];
                float v2 = cacc[m2][dt][2] + oth[m2 * 8 + dt * 4 + 2];
                float v3 = cacc[m2][dt][3] + oth[m2 * 8 + dt * 4 + 3];
                *(float2*)&ctx[((size_t)b * 512 + row) * 512 + col] = make_float2(v0, v1);
                *(float2*)&ctx[((size_t)b * 512 + row + 8) * 512 + col] = make_float2(v2, v3);
            }
        }
    }
}

// ---------------- launch ----------------------------------------------------
extern "C" void kernel_launch(void* const* d_in, const int* in_sizes, int n_in,
                              void* d_out, int out_size)
{
    const float* X   = (const float*)d_in[0];
    const float* w1  = (const float*)d_in[2];
    const float* b1  = (const float*)d_in[3];
    const float* g1  = (const float*)d_in[4];
    const float* be1 = (const float*)d_in[5];
    const float* m1  = (const float*)d_in[6];
    const float* v1  = (const float*)d_in[7];
    const float* w2  = (const float*)d_in[8];
    const float* b2  = (const float*)d_in[9];
    const float* g2  = (const float*)d_in[10];
    const float* be2 = (const float*)d_in[11];
    const float* m2  = (const float*)d_in[12];
    const float* v2  = (const float*)d_in[13];

    float* out  = (float*)d_out;
    float* attn = out + (size_t)4 * 512 * 512;

    float *qkv, *ctx;
    uint32_t *qh, *ql, *kh, *kl, *vth, *vtl;
    cudaGetSymbolAddress((void**)&qkv, g_qkv);
    cudaGetSymbolAddress((void**)&ctx, g_ctx);
    cudaGetSymbolAddress((void**)&qh, g_qh);
    cudaGetSymbolAddress((void**)&ql, g_ql);
    cudaGetSymbolAddress((void**)&kh, g_kh);
    cudaGetSymbolAddress((void**)&kl, g_kl);
    cudaGetSymbolAddress((void**)&vth, g_vth);
    cudaGetSymbolAddress((void**)&vtl, g_vtl);

    cudaFuncSetAttribute(attn_mma_kernel, cudaFuncAttributeMaxDynamicSharedMemorySize, SMEMB);

    dim3 cb(32, 8);

    // 6 launches/iter; attn at idx 4 => ncu capture slot (#10) = attn
    conv_fused_kernel<<<dim3(16, 64, 12), cb>>>(X, w1, b1, g1, be1, m1, v1,
                                                w2, b2, g2, be2, m2, v2, qkv, 0);   // 0
    split_kernel<<<2560, 256>>>(qkv);                                               // 1
    dummy_kernel<<<1, 32>>>();                                                      // 2
    dummy_kernel<<<1, 32>>>();                                                      // 3
    attn_mma_kernel<<<dim3(16, 8, 4), 256, SMEMB>>>(qh, ql, kh, kl, vth, vtl, attn, ctx); // 4
    conv_fused_kernel<<<dim3(16, 64, 4), cb>>>(ctx, w1, b1, g1, be1, m1, v1,
                                               w2, b2, g2, be2, m2, v2, out, 3);    // 5
}